// round 9
// baseline (speedup 1.0000x reference)
#include <cuda_runtime.h>
#include <cuda_fp16.h>
#include <cstdint>

#define SEQ   16384
#define HID   2048
#define EMB   512
#define NCHR  128
#define FAN   2560
#define NCTA  148
#define TPB   1024

// smem layout (bytes)
#define S_W_OFF   0                 // 54 rows * 4096 = 221184
#define S_H_OFF   221184            // 2048 u32 (half2 hi,lo) = 8192
#define PART_OFF  229376            // 56 rows * 8 kc * 4B = 1792
#define SMEM_BYTES 231424

__device__ unsigned int g_ctr;
__device__ __align__(16) unsigned int g_h2[2][HID];       // half2(hi,lo) per element
__device__ __align__(16) __half g_w16[4 * HID * HID];     // fp16 Wh, 32MB
__device__ __align__(16) float g_gx[NCHR * 4 * HID];
__device__ __align__(16) float g_embT[EMB * NCHR];
__device__ __align__(16) float g_hist[(size_t)SEQ * HID];

__device__ __forceinline__ float sigf(float x) { return 1.f / (1.f + __expf(-x)); }
__device__ __forceinline__ float tanh_f(float x) {
    x = fminf(fmaxf(x, -15.f), 15.f);
    float e = __expf(2.f * x);
    return (e - 1.f) / (e + 1.f);
}

__global__ void embTk(const float* __restrict__ emb) {
    int i = blockIdx.x * blockDim.x + threadIdx.x;
    if (i < EMB * NCHR) {
        int k = i / NCHR, c = i % NCHR;
        g_embT[(size_t)k * NCHR + c] = emb[(size_t)c * EMB + k];
    }
}

// fp16 weight conversion + per-call reset (keeps lstm_persist at launch idx 3)
__global__ void w16k(const float* __restrict__ Wf, const float* __restrict__ Wi,
                     const float* __restrict__ Wg, const float* __restrict__ Wo) {
    if (blockIdx.x < 8) {
        int i = blockIdx.x * 256 + threadIdx.x;
        g_h2[0][i] = 0u; g_h2[1][i] = 0u;
        if (i == 0) g_ctr = 0u;
    }
    int rho = blockIdx.x;
    int g = rho >> 11, j = rho & 2047;
    const float* W = (g == 0) ? Wf : (g == 1) ? Wi : (g == 2) ? Wg : Wo;
    const float* row = W + (size_t)j * FAN + EMB;
    __half* dst = g_w16 + (size_t)rho * HID;
    for (int k = threadIdx.x; k < HID; k += 256)
        dst[k] = __float2half_rn(row[k]);
}

__global__ void gxk(const float* __restrict__ Wf, const float* __restrict__ Wi,
                    const float* __restrict__ Wg, const float* __restrict__ Wo,
                    const float* __restrict__ bf, const float* __restrict__ bi,
                    const float* __restrict__ bg, const float* __restrict__ bo) {
    int rho = blockIdx.x;
    int g = rho >> 11, j = rho & 2047;
    const float* W = (g == 0) ? Wf : (g == 1) ? Wi : (g == 2) ? Wg : Wo;
    const float* B = (g == 0) ? bf : (g == 1) ? bi : (g == 2) ? bg : bo;
    const float* row = W + (size_t)j * FAN;
    __shared__ float wx[EMB];
    for (int k = threadIdx.x; k < EMB; k += 128) wx[k] = row[k];
    __syncthreads();
    int c = threadIdx.x;
    float a0 = 0.f, a1 = 0.f, a2 = 0.f, a3 = 0.f;
    #pragma unroll 4
    for (int k = 0; k < EMB; k += 4) {
        a0 = fmaf(wx[k + 0], g_embT[(size_t)(k + 0) * NCHR + c], a0);
        a1 = fmaf(wx[k + 1], g_embT[(size_t)(k + 1) * NCHR + c], a1);
        a2 = fmaf(wx[k + 2], g_embT[(size_t)(k + 2) * NCHR + c], a2);
        a3 = fmaf(wx[k + 3], g_embT[(size_t)(k + 3) * NCHR + c], a3);
    }
    g_gx[(size_t)c * (4 * HID) + rho] = ((a0 + a1) + (a2 + a3)) + B[j];
}

__global__ void __launch_bounds__(TPB, 1)
lstm_persist(const int* __restrict__ seq, float* __restrict__ d_out) {
    extern __shared__ unsigned char smem[];
    float* s_part = (float*)(smem + PART_OFF);

    uint32_t sbase;
    asm("{ .reg .u64 t; cvta.to.shared.u64 t, %1; cvt.u32.u64 %0, t; }"
        : "=r"(sbase) : "l"(smem));

    const int b   = blockIdx.x;
    const int tid = threadIdx.x;
    const int ne  = (b < 124) ? 14 : 13;
    const int e0  = (b < 124) ? 14 * b : 1736 + 13 * (b - 124);
    const int nrows = 4 * ne;
    const int rows_smem = (nrows < 54) ? nrows : 54;

    // fp16 weight rows -> SMEM, 16B-granule XOR swizzle per row (ldmatrix-friendly)
    for (int i = tid; i < rows_smem * 256; i += TPB) {
        int rl = i >> 8, gi = i & 255;
        int G = (rl / ne) * HID + e0 + (rl % ne);
        uint4 v = ((const uint4*)(g_w16 + (size_t)G * HID))[gi];
        uint32_t off = rl * 4096 + ((gi * 16) ^ ((rl & 7) << 4));
        *(uint4*)(smem + S_W_OFF + off) = v;
    }

    const int w = tid >> 5, lane = tid & 31;
    const int tile = w >> 3;            // m-tile 0..3
    const int kc   = w & 7;             // k-chunk of 256

    int rl_lane = tile * 16 + (lane & 15);
    if (rl_lane >= rows_smem) rl_lane = tile * 16;           // clamp (ignored rows)
    const uint32_t swz = (uint32_t)((rl_lane & 7) << 4);
    const uint32_t klo16 = (lane >= 16) ? 16u : 0u;
    const uint32_t a_base = sbase + S_W_OFF + (uint32_t)rl_lane * 4096;

    // B-frag: lanes 0-7 carry cols 0 (h_hi) / 1 (h_lo)
    const uint32_t sel = (lane < 4) ? 0x5410u : 0x7632u;     // low-halves / high-halves
    const int kbase = kc * 256 + (lane & 3) * 2;             // element index

    float c_state = 0.f;
    __syncthreads();

    for (int t = 0; t < SEQ; t++) {
        // gx prefetch (h-independent; overlaps the spin)
        float gx0 = 0.f, gx1 = 0.f, gx2 = 0.f, gx3 = 0.f;
        if (tid < ne) {
            int ch = __ldg(seq + t);
            const float* gp = g_gx + (size_t)ch * (4 * HID) + e0 + tid;
            gx0 = __ldg(gp);
            gx1 = __ldg(gp + HID);
            gx2 = __ldg(gp + 2 * HID);
            gx3 = __ldg(gp + 3 * HID);
        }

        if (t > 0) {
            if (tid == 0) {
                unsigned int tgt = (unsigned int)t * NCTA, v;
                do {
                    asm volatile("ld.acquire.gpu.global.u32 %0, [%1];"
                                 : "=r"(v) : "l"(&g_ctr) : "memory");
                } while (v < tgt);
            }
            __syncthreads();                                 // bar 1
        }

        // stage packed h2 (u32/elem): 512 threads x LDG.128.cv -> STS.128
        if (tid < 512) {
            uint4 v = __ldcv(((const uint4*)g_h2[t & 1]) + tid);
            *(uint4*)(smem + S_H_OFF + tid * 16) = v;
        }
        __syncthreads();                                     // bar 2

        // HMMA mainloop: 16 k-tiles, 2 accumulator chains
        float c0 = 0.f, c1 = 0.f, c2 = 0.f, c3 = 0.f;
        float d0 = 0.f, d1 = 0.f, d2 = 0.f, d3 = 0.f;
        #pragma unroll
        for (int kt = 0; kt < 16; kt++) {
            uint32_t byt = (uint32_t)(kc * 512 + kt * 32) + klo16;
            uint32_t a_addr = a_base + (byt ^ swz);
            uint32_t a0, a1, a2, a3;
            asm volatile("ldmatrix.sync.aligned.m8n8.x4.shared.b16 {%0,%1,%2,%3}, [%4];"
                         : "=r"(a0), "=r"(a1), "=r"(a2), "=r"(a3) : "r"(a_addr));
            uint32_t bb0 = 0u, bb1 = 0u;
            if (lane < 8) {
                uint2 v0 = *(const uint2*)(smem + S_H_OFF + (kbase + kt * 16) * 4);
                uint2 v1 = *(const uint2*)(smem + S_H_OFF + (kbase + kt * 16 + 8) * 4);
                asm("prmt.b32 %0, %1, %2, %3;" : "=r"(bb0) : "r"(v0.x), "r"(v0.y), "r"(sel));
                asm("prmt.b32 %0, %1, %2, %3;" : "=r"(bb1) : "r"(v1.x), "r"(v1.y), "r"(sel));
            }
            if (kt & 1)
                asm volatile("mma.sync.aligned.m16n8k16.row.col.f32.f16.f16.f32 "
                             "{%0,%1,%2,%3}, {%4,%5,%6,%7}, {%8,%9}, {%0,%1,%2,%3};"
                             : "+f"(d0), "+f"(d1), "+f"(d2), "+f"(d3)
                             : "r"(a0), "r"(a1), "r"(a2), "r"(a3), "r"(bb0), "r"(bb1));
            else
                asm volatile("mma.sync.aligned.m16n8k16.row.col.f32.f16.f16.f32 "
                             "{%0,%1,%2,%3}, {%4,%5,%6,%7}, {%8,%9}, {%0,%1,%2,%3};"
                             : "+f"(c0), "+f"(c1), "+f"(c2), "+f"(c3)
                             : "r"(a0), "r"(a1), "r"(a2), "r"(a3), "r"(bb0), "r"(bb1));
        }
        c0 += d0; c1 += d1; c2 += d2; c3 += d3;

        // partials: row-major s_part[row][kc]  (col0+col1 = w.h_hi + w.h_lo)
        if ((lane & 3) == 0) {
            int r0 = tile * 16 + (lane >> 2), r1 = r0 + 8;
            if (r0 < rows_smem) s_part[r0 * 8 + kc] = c0 + c1;
            if (r1 < rows_smem) s_part[r1 * 8 + kc] = c2 + c3;
        }

        // overflow rows 54,55 (ne==14): FFMA side-path from L2 weights, staged h2
        if (ne == 14 && tile == 3) {
            int k0 = kc * 256 + lane * 8;
            uint4 hv0 = *(const uint4*)(smem + S_H_OFF + k0 * 4);
            uint4 hv1 = *(const uint4*)(smem + S_H_OFF + k0 * 4 + 16);
            float h[8];
            {
                float2 f;
                f = __half22float2(*(__half2*)&hv0.x); h[0] = f.x + f.y;
                f = __half22float2(*(__half2*)&hv0.y); h[1] = f.x + f.y;
                f = __half22float2(*(__half2*)&hv0.z); h[2] = f.x + f.y;
                f = __half22float2(*(__half2*)&hv0.w); h[3] = f.x + f.y;
                f = __half22float2(*(__half2*)&hv1.x); h[4] = f.x + f.y;
                f = __half22float2(*(__half2*)&hv1.y); h[5] = f.x + f.y;
                f = __half22float2(*(__half2*)&hv1.z); h[6] = f.x + f.y;
                f = __half22float2(*(__half2*)&hv1.w); h[7] = f.x + f.y;
            }
            #pragma unroll
            for (int rr = 0; rr < 2; rr++) {
                uint4 wv = __ldg((const uint4*)(g_w16 + (size_t)(3 * HID + e0 + 12 + rr) * HID + k0));
                float2 w0 = __half22float2(*(__half2*)&wv.x);
                float2 w1 = __half22float2(*(__half2*)&wv.y);
                float2 w2 = __half22float2(*(__half2*)&wv.z);
                float2 w3 = __half22float2(*(__half2*)&wv.w);
                float acc = w0.x * h[0];
                acc = fmaf(w0.y, h[1], acc);
                acc = fmaf(w1.x, h[2], acc);
                acc = fmaf(w1.y, h[3], acc);
                acc = fmaf(w2.x, h[4], acc);
                acc = fmaf(w2.y, h[5], acc);
                acc = fmaf(w3.x, h[6], acc);
                acc = fmaf(w3.y, h[7], acc);
                #pragma unroll
                for (int o = 16; o > 0; o >>= 1)
                    acc += __shfl_xor_sync(0xffffffffu, acc, o);
                if (lane == 0) s_part[(54 + rr) * 8 + kc] = acc;
            }
        }
        __syncthreads();                                     // bar 3

        // combine (warp 0 only) -> store h2 -> warp-scope release
        if (tid < ne) {
            float p[4];
            #pragma unroll
            for (int g = 0; g < 4; g++) {
                int rl = g * ne + tid;
                float4 q0 = *(const float4*)(s_part + rl * 8);
                float4 q1 = *(const float4*)(s_part + rl * 8 + 4);
                p[g] = ((q0.x + q0.y) + (q0.z + q0.w)) + ((q1.x + q1.y) + (q1.z + q1.w));
            }
            float fg = sigf(p[0] + gx0);
            float ig = sigf(p[1] + gx1);
            float gg = tanh_f(p[2] + gx2);
            float og = sigf(p[3] + gx3);
            c_state = fg * c_state + ig * gg;
            float hnew = og * tanh_f(c_state);
            int jj = e0 + tid;
            __half hi = __float2half_rn(hnew);
            __half lo = __float2half_rn(hnew - __half2float(hi));
            unsigned int h2v = (unsigned int)__half_as_ushort(hi)
                             | ((unsigned int)__half_as_ushort(lo) << 16);
            __stcg(&g_h2[(t + 1) & 1][jj], h2v);
            g_hist[(size_t)t * HID + jj] = hnew;
            if (t == SEQ - 1) {
                d_out[(size_t)SEQ * NCHR + jj] = hnew;
                d_out[(size_t)SEQ * NCHR + HID + jj] = c_state;
            }
        }
        if (w == 0) {
            __syncwarp();                                    // HB: lanes 0..13 stores -> tid0
            if (lane == 0)
                asm volatile("red.release.gpu.global.add.u32 [%0], %1;"
                             :: "l"(&g_ctr), "r"(1u) : "memory");
        }
    }
}

__global__ void __launch_bounds__(128)
logitsk(const float* __restrict__ Wfc, const float* __restrict__ bfc,
        float* __restrict__ out) {
    __shared__ float hs[16][129];
    const int t0 = blockIdx.x * 16;
    const int c = threadIdx.x;
    float acc[16];
    float bias = bfc[c];
    #pragma unroll
    for (int i = 0; i < 16; i++) acc[i] = bias;

    for (int k0 = 0; k0 < HID; k0 += 128) {
        __syncthreads();
        #pragma unroll
        for (int i = 0; i < 16; i++)
            hs[i][c] = g_hist[(size_t)(t0 + i) * HID + k0 + c];
        __syncthreads();
        #pragma unroll 4
        for (int kk = 0; kk < 128; kk++) {
            float wv = __ldg(Wfc + (size_t)c * HID + k0 + kk);
            #pragma unroll
            for (int i = 0; i < 16; i++)
                acc[i] = fmaf(hs[i][kk], wv, acc[i]);
        }
    }
    #pragma unroll
    for (int i = 0; i < 16; i++)
        out[(size_t)(t0 + i) * NCHR + c] = acc[i];
}

extern "C" void kernel_launch(void* const* d_in, const int* in_sizes, int n_in,
                              void* d_out, int out_size) {
    const int*   seq = (const int*)d_in[0];
    const float* emb = (const float*)d_in[1];
    const float* Wf  = (const float*)d_in[2];
    const float* bf  = (const float*)d_in[3];
    const float* Wi  = (const float*)d_in[4];
    const float* bi  = (const float*)d_in[5];
    const float* Wg  = (const float*)d_in[6];
    const float* bg  = (const float*)d_in[7];
    const float* Wo  = (const float*)d_in[8];
    const float* bo  = (const float*)d_in[9];
    const float* Wfc = (const float*)d_in[10];
    const float* bfc = (const float*)d_in[11];
    float* out = (float*)d_out;

    cudaFuncSetAttribute(lstm_persist,
                         cudaFuncAttributeMaxDynamicSharedMemorySize, SMEM_BYTES);

    embTk<<<(EMB * NCHR + 255) / 256, 256>>>(emb);                    // launch 0
    w16k<<<4 * HID, 256>>>(Wf, Wi, Wg, Wo);                           // launch 1 (+reset)
    gxk<<<4 * HID, 128>>>(Wf, Wi, Wg, Wo, bf, bi, bg, bo);            // launch 2
    lstm_persist<<<NCTA, TPB, SMEM_BYTES>>>(seq, out);                // launch 3 (ncu slot)
    logitsk<<<SEQ / 16, 128>>>(Wfc, bfc, out);                        // launch 4
}

// round 10
// speedup vs baseline: 1.0001x; 1.0001x over previous
#include <cuda_runtime.h>
#include <cuda_fp16.h>
#include <cstdint>

#define SEQ   16384
#define HID   2048
#define EMB   512
#define NCHR  128
#define FAN   2560
#define NCTA  148
#define TPB   1024

// smem layout (bytes)
#define S_W_OFF   0                 // 54 rows * 4096 = 221184
#define S_H_OFF   221184            // 2048 u32 (half2 hi,lo) = 8192
#define PART_OFF  229376            // 56 rows * 8 kc * 4B = 1792
#define SMEM_BYTES 231424

__device__ unsigned int g_ctr;
__device__ __align__(16) unsigned int g_h2[2][HID];       // half2(hi,lo) per element
__device__ __align__(16) __half g_w16[4 * HID * HID];     // fp16 Wh, 32MB
__device__ __align__(16) float g_gx[NCHR * 4 * HID];
__device__ __align__(16) float g_embT[EMB * NCHR];
__device__ __align__(16) float g_hist[(size_t)SEQ * HID];

__device__ __forceinline__ float sigf(float x) { return 1.f / (1.f + __expf(-x)); }
__device__ __forceinline__ float tanh_f(float x) {
    x = fminf(fmaxf(x, -15.f), 15.f);
    float e = __expf(2.f * x);
    return (e - 1.f) / (e + 1.f);
}

__global__ void embTk(const float* __restrict__ emb) {
    int i = blockIdx.x * blockDim.x + threadIdx.x;
    if (i < EMB * NCHR) {
        int k = i / NCHR, c = i % NCHR;
        g_embT[(size_t)k * NCHR + c] = emb[(size_t)c * EMB + k];
    }
}

// fp16 weight conversion + per-call reset (keeps lstm_persist at launch idx 3)
__global__ void w16k(const float* __restrict__ Wf, const float* __restrict__ Wi,
                     const float* __restrict__ Wg, const float* __restrict__ Wo) {
    if (blockIdx.x < 8) {
        int i = blockIdx.x * 256 + threadIdx.x;
        g_h2[0][i] = 0u; g_h2[1][i] = 0u;
        if (i == 0) g_ctr = 0u;
    }
    int rho = blockIdx.x;
    int g = rho >> 11, j = rho & 2047;
    const float* W = (g == 0) ? Wf : (g == 1) ? Wi : (g == 2) ? Wg : Wo;
    const float* row = W + (size_t)j * FAN + EMB;
    __half* dst = g_w16 + (size_t)rho * HID;
    for (int k = threadIdx.x; k < HID; k += 256)
        dst[k] = __float2half_rn(row[k]);
}

__global__ void gxk(const float* __restrict__ Wf, const float* __restrict__ Wi,
                    const float* __restrict__ Wg, const float* __restrict__ Wo,
                    const float* __restrict__ bf, const float* __restrict__ bi,
                    const float* __restrict__ bg, const float* __restrict__ bo) {
    int rho = blockIdx.x;
    int g = rho >> 11, j = rho & 2047;
    const float* W = (g == 0) ? Wf : (g == 1) ? Wi : (g == 2) ? Wg : Wo;
    const float* B = (g == 0) ? bf : (g == 1) ? bi : (g == 2) ? bg : bo;
    const float* row = W + (size_t)j * FAN;
    __shared__ float wx[EMB];
    for (int k = threadIdx.x; k < EMB; k += 128) wx[k] = row[k];
    __syncthreads();
    int c = threadIdx.x;
    float a0 = 0.f, a1 = 0.f, a2 = 0.f, a3 = 0.f;
    #pragma unroll 4
    for (int k = 0; k < EMB; k += 4) {
        a0 = fmaf(wx[k + 0], g_embT[(size_t)(k + 0) * NCHR + c], a0);
        a1 = fmaf(wx[k + 1], g_embT[(size_t)(k + 1) * NCHR + c], a1);
        a2 = fmaf(wx[k + 2], g_embT[(size_t)(k + 2) * NCHR + c], a2);
        a3 = fmaf(wx[k + 3], g_embT[(size_t)(k + 3) * NCHR + c], a3);
    }
    g_gx[(size_t)c * (4 * HID) + rho] = ((a0 + a1) + (a2 + a3)) + B[j];
}

__global__ void __launch_bounds__(TPB, 1)
lstm_persist(const int* __restrict__ seq, float* __restrict__ d_out) {
    extern __shared__ unsigned char smem[];
    float* s_part = (float*)(smem + PART_OFF);

    uint32_t sbase;
    asm("{ .reg .u64 t; cvta.to.shared.u64 t, %1; cvt.u32.u64 %0, t; }"
        : "=r"(sbase) : "l"(smem));

    const int b   = blockIdx.x;
    const int tid = threadIdx.x;
    const int ne  = (b < 124) ? 14 : 13;
    const int e0  = (b < 124) ? 14 * b : 1736 + 13 * (b - 124);
    const int nrows = 4 * ne;
    const int rows_smem = (nrows < 54) ? nrows : 54;

    // fp16 weight rows -> SMEM, 16B-granule XOR swizzle per row (ldmatrix-friendly)
    for (int i = tid; i < rows_smem * 256; i += TPB) {
        int rl = i >> 8, gi = i & 255;
        int G = (rl / ne) * HID + e0 + (rl % ne);
        uint4 v = ((const uint4*)(g_w16 + (size_t)G * HID))[gi];
        uint32_t off = rl * 4096 + ((gi * 16) ^ ((rl & 7) << 4));
        *(uint4*)(smem + S_W_OFF + off) = v;
    }

    const int w = tid >> 5, lane = tid & 31;
    const int tile = w >> 3;            // m-tile 0..3
    const int kc   = w & 7;             // k-chunk of 256

    int rl_lane = tile * 16 + (lane & 15);
    if (rl_lane >= rows_smem) rl_lane = tile * 16;           // clamp (ignored rows)
    const uint32_t swz = (uint32_t)((rl_lane & 7) << 4);
    const uint32_t klo16 = (lane >= 16) ? 16u : 0u;
    const uint32_t a_base = sbase + S_W_OFF + (uint32_t)rl_lane * 4096;

    // B-frag: lanes 0-7 carry cols 0 (h_hi) / 1 (h_lo)
    const uint32_t sel = (lane < 4) ? 0x5410u : 0x7632u;     // low-halves / high-halves
    const int kbase = kc * 256 + (lane & 3) * 2;             // element index

    float c_state = 0.f;
    __syncthreads();

    for (int t = 0; t < SEQ; t++) {
        // gx prefetch (h-independent; overlaps the spin)
        float gx0 = 0.f, gx1 = 0.f, gx2 = 0.f, gx3 = 0.f;
        if (tid < ne) {
            int ch = __ldg(seq + t);
            const float* gp = g_gx + (size_t)ch * (4 * HID) + e0 + tid;
            gx0 = __ldg(gp);
            gx1 = __ldg(gp + HID);
            gx2 = __ldg(gp + 2 * HID);
            gx3 = __ldg(gp + 3 * HID);
        }

        if (t > 0) {
            if (tid == 0) {
                unsigned int tgt = (unsigned int)t * NCTA, v;
                do {
                    asm volatile("ld.acquire.gpu.global.u32 %0, [%1];"
                                 : "=r"(v) : "l"(&g_ctr) : "memory");
                } while (v < tgt);
            }
            __syncthreads();                                 // bar 1
        }

        // stage packed h2 (u32/elem): 512 threads x LDG.128.cv -> STS.128
        if (tid < 512) {
            uint4 v = __ldcv(((const uint4*)g_h2[t & 1]) + tid);
            *(uint4*)(smem + S_H_OFF + tid * 16) = v;
        }
        __syncthreads();                                     // bar 2

        // HMMA mainloop: 16 k-tiles, 2 accumulator chains
        float c0 = 0.f, c1 = 0.f, c2 = 0.f, c3 = 0.f;
        float d0 = 0.f, d1 = 0.f, d2 = 0.f, d3 = 0.f;
        #pragma unroll
        for (int kt = 0; kt < 16; kt++) {
            uint32_t byt = (uint32_t)(kc * 512 + kt * 32) + klo16;
            uint32_t a_addr = a_base + (byt ^ swz);
            uint32_t a0, a1, a2, a3;
            asm volatile("ldmatrix.sync.aligned.m8n8.x4.shared.b16 {%0,%1,%2,%3}, [%4];"
                         : "=r"(a0), "=r"(a1), "=r"(a2), "=r"(a3) : "r"(a_addr));
            uint32_t bb0 = 0u, bb1 = 0u;
            if (lane < 8) {
                uint2 v0 = *(const uint2*)(smem + S_H_OFF + (kbase + kt * 16) * 4);
                uint2 v1 = *(const uint2*)(smem + S_H_OFF + (kbase + kt * 16 + 8) * 4);
                asm("prmt.b32 %0, %1, %2, %3;" : "=r"(bb0) : "r"(v0.x), "r"(v0.y), "r"(sel));
                asm("prmt.b32 %0, %1, %2, %3;" : "=r"(bb1) : "r"(v1.x), "r"(v1.y), "r"(sel));
            }
            if (kt & 1)
                asm volatile("mma.sync.aligned.m16n8k16.row.col.f32.f16.f16.f32 "
                             "{%0,%1,%2,%3}, {%4,%5,%6,%7}, {%8,%9}, {%0,%1,%2,%3};"
                             : "+f"(d0), "+f"(d1), "+f"(d2), "+f"(d3)
                             : "r"(a0), "r"(a1), "r"(a2), "r"(a3), "r"(bb0), "r"(bb1));
            else
                asm volatile("mma.sync.aligned.m16n8k16.row.col.f32.f16.f16.f32 "
                             "{%0,%1,%2,%3}, {%4,%5,%6,%7}, {%8,%9}, {%0,%1,%2,%3};"
                             : "+f"(c0), "+f"(c1), "+f"(c2), "+f"(c3)
                             : "r"(a0), "r"(a1), "r"(a2), "r"(a3), "r"(bb0), "r"(bb1));
        }
        c0 += d0; c1 += d1; c2 += d2; c3 += d3;

        // partials: row-major s_part[row][kc]  (col0+col1 = w.h_hi + w.h_lo)
        if ((lane & 3) == 0) {
            int r0 = tile * 16 + (lane >> 2), r1 = r0 + 8;
            if (r0 < rows_smem) s_part[r0 * 8 + kc] = c0 + c1;
            if (r1 < rows_smem) s_part[r1 * 8 + kc] = c2 + c3;
        }

        // overflow rows 54,55 (ne==14): FFMA side-path from L2 weights, staged h2
        if (ne == 14 && tile == 3) {
            int k0 = kc * 256 + lane * 8;
            uint4 hv0 = *(const uint4*)(smem + S_H_OFF + k0 * 4);
            uint4 hv1 = *(const uint4*)(smem + S_H_OFF + k0 * 4 + 16);
            float h[8];
            {
                float2 f;
                f = __half22float2(*(__half2*)&hv0.x); h[0] = f.x + f.y;
                f = __half22float2(*(__half2*)&hv0.y); h[1] = f.x + f.y;
                f = __half22float2(*(__half2*)&hv0.z); h[2] = f.x + f.y;
                f = __half22float2(*(__half2*)&hv0.w); h[3] = f.x + f.y;
                f = __half22float2(*(__half2*)&hv1.x); h[4] = f.x + f.y;
                f = __half22float2(*(__half2*)&hv1.y); h[5] = f.x + f.y;
                f = __half22float2(*(__half2*)&hv1.z); h[6] = f.x + f.y;
                f = __half22float2(*(__half2*)&hv1.w); h[7] = f.x + f.y;
            }
            #pragma unroll
            for (int rr = 0; rr < 2; rr++) {
                uint4 wv = __ldg((const uint4*)(g_w16 + (size_t)(3 * HID + e0 + 12 + rr) * HID + k0));
                float2 w0 = __half22float2(*(__half2*)&wv.x);
                float2 w1 = __half22float2(*(__half2*)&wv.y);
                float2 w2 = __half22float2(*(__half2*)&wv.z);
                float2 w3 = __half22float2(*(__half2*)&wv.w);
                float acc = w0.x * h[0];
                acc = fmaf(w0.y, h[1], acc);
                acc = fmaf(w1.x, h[2], acc);
                acc = fmaf(w1.y, h[3], acc);
                acc = fmaf(w2.x, h[4], acc);
                acc = fmaf(w2.y, h[5], acc);
                acc = fmaf(w3.x, h[6], acc);
                acc = fmaf(w3.y, h[7], acc);
                #pragma unroll
                for (int o = 16; o > 0; o >>= 1)
                    acc += __shfl_xor_sync(0xffffffffu, acc, o);
                if (lane == 0) s_part[(54 + rr) * 8 + kc] = acc;
            }
        }
        __syncthreads();                                     // bar 3

        // combine (warp 0 only) -> store h2 -> warp-scope release
        if (tid < ne) {
            float p[4];
            #pragma unroll
            for (int g = 0; g < 4; g++) {
                int rl = g * ne + tid;
                float4 q0 = *(const float4*)(s_part + rl * 8);
                float4 q1 = *(const float4*)(s_part + rl * 8 + 4);
                p[g] = ((q0.x + q0.y) + (q0.z + q0.w)) + ((q1.x + q1.y) + (q1.z + q1.w));
            }
            float fg = sigf(p[0] + gx0);
            float ig = sigf(p[1] + gx1);
            float gg = tanh_f(p[2] + gx2);
            float og = sigf(p[3] + gx3);
            c_state = fg * c_state + ig * gg;
            float hnew = og * tanh_f(c_state);
            int jj = e0 + tid;
            __half hi = __float2half_rn(hnew);
            __half lo = __float2half_rn(hnew - __half2float(hi));
            unsigned int h2v = (unsigned int)__half_as_ushort(hi)
                             | ((unsigned int)__half_as_ushort(lo) << 16);
            __stcg(&g_h2[(t + 1) & 1][jj], h2v);
            g_hist[(size_t)t * HID + jj] = hnew;
            if (t == SEQ - 1) {
                d_out[(size_t)SEQ * NCHR + jj] = hnew;
                d_out[(size_t)SEQ * NCHR + HID + jj] = c_state;
            }
        }
        if (w == 0) {
            __syncwarp();                                    // HB: lanes 0..13 stores -> tid0
            if (lane == 0)
                asm volatile("red.release.gpu.global.add.u32 [%0], %1;"
                             :: "l"(&g_ctr), "r"(1u) : "memory");
        }
    }
}

__global__ void __launch_bounds__(128)
logitsk(const float* __restrict__ Wfc, const float* __restrict__ bfc,
        float* __restrict__ out) {
    __shared__ float hs[16][129];
    const int t0 = blockIdx.x * 16;
    const int c = threadIdx.x;
    float acc[16];
    float bias = bfc[c];
    #pragma unroll
    for (int i = 0; i < 16; i++) acc[i] = bias;

    for (int k0 = 0; k0 < HID; k0 += 128) {
        __syncthreads();
        #pragma unroll
        for (int i = 0; i < 16; i++)
            hs[i][c] = g_hist[(size_t)(t0 + i) * HID + k0 + c];
        __syncthreads();
        #pragma unroll 4
        for (int kk = 0; kk < 128; kk++) {
            float wv = __ldg(Wfc + (size_t)c * HID + k0 + kk);
            #pragma unroll
            for (int i = 0; i < 16; i++)
                acc[i] = fmaf(hs[i][kk], wv, acc[i]);
        }
    }
    #pragma unroll
    for (int i = 0; i < 16; i++)
        out[(size_t)(t0 + i) * NCHR + c] = acc[i];
}

extern "C" void kernel_launch(void* const* d_in, const int* in_sizes, int n_in,
                              void* d_out, int out_size) {
    const int*   seq = (const int*)d_in[0];
    const float* emb = (const float*)d_in[1];
    const float* Wf  = (const float*)d_in[2];
    const float* bf  = (const float*)d_in[3];
    const float* Wi  = (const float*)d_in[4];
    const float* bi  = (const float*)d_in[5];
    const float* Wg  = (const float*)d_in[6];
    const float* bg  = (const float*)d_in[7];
    const float* Wo  = (const float*)d_in[8];
    const float* bo  = (const float*)d_in[9];
    const float* Wfc = (const float*)d_in[10];
    const float* bfc = (const float*)d_in[11];
    float* out = (float*)d_out;

    cudaFuncSetAttribute(lstm_persist,
                         cudaFuncAttributeMaxDynamicSharedMemorySize, SMEM_BYTES);

    embTk<<<(EMB * NCHR + 255) / 256, 256>>>(emb);                    // launch 0
    w16k<<<4 * HID, 256>>>(Wf, Wi, Wg, Wo);                           // launch 1 (+reset)
    gxk<<<4 * HID, 128>>>(Wf, Wi, Wg, Wo, bf, bi, bg, bo);            // launch 2
    lstm_persist<<<NCTA, TPB, SMEM_BYTES>>>(seq, out);                // launch 3 (ncu slot)
    logitsk<<<SEQ / 16, 128>>>(Wfc, bfc, out);                        // launch 4
}

// round 13
// speedup vs baseline: 1.0221x; 1.0219x over previous
#include <cuda_runtime.h>
#include <cuda_fp16.h>
#include <cstdint>

#define SEQ   16384
#define HID   2048
#define EMB   512
#define NCHR  128
#define FAN   2560
#define NCTA  148
#define TPB   1024
#define NREP  4

// smem layout (bytes)
#define S_W_OFF   0                 // 54 rows * 4096 = 221184
#define S_H_OFF   221184            // 2048 u32 (half2 hi,lo) = 8192
#define PART_OFF  229376            // 56 rows * 8 kc * 4B = 1792
#define SMEM_BYTES 231424

// tagged, replicated hidden state: u64 = { lo32 = half2(hi,lo), hi32 = step tag }
__device__ __align__(16) unsigned long long g_ht[2][NREP][HID];   // 128 KB
__device__ __align__(16) __half g_w16[4 * HID * HID];             // fp16 Wh, 32MB
__device__ __align__(16) float g_gx[NCHR * 4 * HID];
__device__ __align__(16) float g_embT[EMB * NCHR];
__device__ __align__(16) float g_hist[(size_t)SEQ * HID];

__device__ __forceinline__ float sigf(float x) { return 1.f / (1.f + __expf(-x)); }
__device__ __forceinline__ float tanh_f(float x) {
    x = fminf(fmaxf(x, -15.f), 15.f);
    float e = __expf(2.f * x);
    return (e - 1.f) / (e + 1.f);
}

__global__ void embTk(const float* __restrict__ emb) {
    int i = blockIdx.x * blockDim.x + threadIdx.x;
    if (i < EMB * NCHR) {
        int k = i / NCHR, c = i % NCHR;
        g_embT[(size_t)k * NCHR + c] = emb[(size_t)c * EMB + k];
    }
}

// fp16 weight conversion + per-call reset of tagged h buffers
__global__ void w16k(const float* __restrict__ Wf, const float* __restrict__ Wi,
                     const float* __restrict__ Wg, const float* __restrict__ Wo) {
    if (blockIdx.x < 8) {
        int i = blockIdx.x * 256 + threadIdx.x;   // 0..2047
        #pragma unroll
        for (int r = 0; r < NREP; r++) {
            g_ht[0][r][i] = 0ull;                          // h=0, tag=0  (step 0 reads this)
            g_ht[1][r][i] = 0xFFFFFFFF00000000ull;         // invalid tag
        }
    }
    int rho = blockIdx.x;
    int g = rho >> 11, j = rho & 2047;
    const float* W = (g == 0) ? Wf : (g == 1) ? Wi : (g == 2) ? Wg : Wo;
    const float* row = W + (size_t)j * FAN + EMB;
    __half* dst = g_w16 + (size_t)rho * HID;
    for (int k = threadIdx.x; k < HID; k += 256)
        dst[k] = __float2half_rn(row[k]);
}

__global__ void gxk(const float* __restrict__ Wf, const float* __restrict__ Wi,
                    const float* __restrict__ Wg, const float* __restrict__ Wo,
                    const float* __restrict__ bf, const float* __restrict__ bi,
                    const float* __restrict__ bg, const float* __restrict__ bo) {
    int rho = blockIdx.x;
    int g = rho >> 11, j = rho & 2047;
    const float* W = (g == 0) ? Wf : (g == 1) ? Wi : (g == 2) ? Wg : Wo;
    const float* B = (g == 0) ? bf : (g == 1) ? bi : (g == 2) ? bg : bo;
    const float* row = W + (size_t)j * FAN;
    __shared__ float wx[EMB];
    for (int k = threadIdx.x; k < EMB; k += 128) wx[k] = row[k];
    __syncthreads();
    int c = threadIdx.x;
    float a0 = 0.f, a1 = 0.f, a2 = 0.f, a3 = 0.f;
    #pragma unroll 4
    for (int k = 0; k < EMB; k += 4) {
        a0 = fmaf(wx[k + 0], g_embT[(size_t)(k + 0) * NCHR + c], a0);
        a1 = fmaf(wx[k + 1], g_embT[(size_t)(k + 1) * NCHR + c], a1);
        a2 = fmaf(wx[k + 2], g_embT[(size_t)(k + 2) * NCHR + c], a2);
        a3 = fmaf(wx[k + 3], g_embT[(size_t)(k + 3) * NCHR + c], a3);
    }
    g_gx[(size_t)c * (4 * HID) + rho] = ((a0 + a1) + (a2 + a3)) + B[j];
}

__global__ void __launch_bounds__(TPB, 1)
lstm_persist(const int* __restrict__ seq, float* __restrict__ d_out) {
    extern __shared__ unsigned char smem[];
    float* s_part = (float*)(smem + PART_OFF);

    uint32_t sbase;
    asm("{ .reg .u64 t; cvta.to.shared.u64 t, %1; cvt.u32.u64 %0, t; }"
        : "=r"(sbase) : "l"(smem));

    const int b   = blockIdx.x;
    const int tid = threadIdx.x;
    const int ne  = (b < 124) ? 14 : 13;
    const int e0  = (b < 124) ? 14 * b : 1736 + 13 * (b - 124);
    const int nrows = 4 * ne;
    const int rows_smem = (nrows < 54) ? nrows : 54;
    const int rep = b & (NREP - 1);

    // fp16 weight rows -> SMEM, 16B-granule XOR swizzle per row (ldmatrix-friendly)
    for (int i = tid; i < rows_smem * 256; i += TPB) {
        int rl = i >> 8, gi = i & 255;
        int G = (rl / ne) * HID + e0 + (rl % ne);
        uint4 v = ((const uint4*)(g_w16 + (size_t)G * HID))[gi];
        uint32_t off = rl * 4096 + ((gi * 16) ^ ((rl & 7) << 4));
        *(uint4*)(smem + S_W_OFF + off) = v;
    }

    const int w = tid >> 5, lane = tid & 31;
    const int tile = w >> 3;            // m-tile 0..3
    const int kc   = w & 7;             // k-chunk of 256

    int rl_lane = tile * 16 + (lane & 15);
    if (rl_lane >= rows_smem) rl_lane = tile * 16;
    const uint32_t swz = (uint32_t)((rl_lane & 7) << 4);
    const uint32_t klo16 = (lane >= 16) ? 16u : 0u;
    const uint32_t a_base = sbase + S_W_OFF + (uint32_t)rl_lane * 4096;

    // B-frag: lanes 0-7 carry cols 0 (h_hi) / 1 (h_lo)
    const uint32_t sel = (lane < 4) ? 0x5410u : 0x7632u;
    const int kbase = kc * 256 + (lane & 3) * 2;

    float c_state = 0.f;
    __syncthreads();

    for (int t = 0; t < SEQ; t++) {
        // gx prefetch (h-independent; overlaps the staging poll)
        float gx0 = 0.f, gx1 = 0.f, gx2 = 0.f, gx3 = 0.f;
        if (tid < ne) {
            int ch = __ldg(seq + t);
            const float* gp = g_gx + (size_t)ch * (4 * HID) + e0 + tid;
            gx0 = __ldg(gp);
            gx1 = __ldg(gp + HID);
            gx2 = __ldg(gp + 2 * HID);
            gx3 = __ldg(gp + 3 * HID);
        }

        // ---- tagged staging with MORALLY-STRONG 8B loads (single-copy atomic):
        // each thread owns elements 2*tid, 2*tid+1; tag(hi32)==t guards payload(lo32).
        {
            const unsigned long long* p0 = &g_ht[t & 1][rep][2 * tid];
            const unsigned int tg = (unsigned int)t;
            unsigned long long v0, v1;
            do {
                asm volatile("ld.relaxed.gpu.global.b64 %0, [%1];"
                             : "=l"(v0) : "l"(p0) : "memory");
            } while ((unsigned int)(v0 >> 32) != tg);
            do {
                asm volatile("ld.relaxed.gpu.global.b64 %0, [%1];"
                             : "=l"(v1) : "l"(p0 + 1) : "memory");
            } while ((unsigned int)(v1 >> 32) != tg);
            *(uint2*)(smem + S_H_OFF + tid * 8) =
                make_uint2((unsigned int)v0, (unsigned int)v1);
        }
        __syncthreads();     // bar A (also orders prev-step s_part reads before rewrites)

        // HMMA mainloop: 16 k-tiles, 2 accumulator chains
        float c0 = 0.f, c1 = 0.f, c2 = 0.f, c3 = 0.f;
        float d0 = 0.f, d1 = 0.f, d2 = 0.f, d3 = 0.f;
        #pragma unroll
        for (int kt = 0; kt < 16; kt++) {
            uint32_t byt = (uint32_t)(kc * 512 + kt * 32) + klo16;
            uint32_t a_addr = a_base + (byt ^ swz);
            uint32_t a0, a1, a2, a3;
            asm volatile("ldmatrix.sync.aligned.m8n8.x4.shared.b16 {%0,%1,%2,%3}, [%4];"
                         : "=r"(a0), "=r"(a1), "=r"(a2), "=r"(a3) : "r"(a_addr));
            uint32_t bb0 = 0u, bb1 = 0u;
            if (lane < 8) {
                uint2 v0 = *(const uint2*)(smem + S_H_OFF + (kbase + kt * 16) * 4);
                uint2 v1 = *(const uint2*)(smem + S_H_OFF + (kbase + kt * 16 + 8) * 4);
                asm("prmt.b32 %0, %1, %2, %3;" : "=r"(bb0) : "r"(v0.x), "r"(v0.y), "r"(sel));
                asm("prmt.b32 %0, %1, %2, %3;" : "=r"(bb1) : "r"(v1.x), "r"(v1.y), "r"(sel));
            }
            if (kt & 1)
                asm volatile("mma.sync.aligned.m16n8k16.row.col.f32.f16.f16.f32 "
                             "{%0,%1,%2,%3}, {%4,%5,%6,%7}, {%8,%9}, {%0,%1,%2,%3};"
                             : "+f"(d0), "+f"(d1), "+f"(d2), "+f"(d3)
                             : "r"(a0), "r"(a1), "r"(a2), "r"(a3), "r"(bb0), "r"(bb1));
            else
                asm volatile("mma.sync.aligned.m16n8k16.row.col.f32.f16.f16.f32 "
                             "{%0,%1,%2,%3}, {%4,%5,%6,%7}, {%8,%9}, {%0,%1,%2,%3};"
                             : "+f"(c0), "+f"(c1), "+f"(c2), "+f"(c3)
                             : "r"(a0), "r"(a1), "r"(a2), "r"(a3), "r"(bb0), "r"(bb1));
        }
        c0 += d0; c1 += d1; c2 += d2; c3 += d3;

        if ((lane & 3) == 0) {
            int r0 = tile * 16 + (lane >> 2), r1 = r0 + 8;
            if (r0 < rows_smem) s_part[r0 * 8 + kc] = c0 + c1;
            if (r1 < rows_smem) s_part[r1 * 8 + kc] = c2 + c3;
        }

        // overflow rows 54,55 (ne==14): FFMA side-path (L2 weights, staged h2)
        if (ne == 14 && tile == 3) {
            int k0 = kc * 256 + lane * 8;
            uint4 hv0 = *(const uint4*)(smem + S_H_OFF + k0 * 4);
            uint4 hv1 = *(const uint4*)(smem + S_H_OFF + k0 * 4 + 16);
            float h[8];
            {
                float2 f;
                f = __half22float2(*(__half2*)&hv0.x); h[0] = f.x + f.y;
                f = __half22float2(*(__half2*)&hv0.y); h[1] = f.x + f.y;
                f = __half22float2(*(__half2*)&hv0.z); h[2] = f.x + f.y;
                f = __half22float2(*(__half2*)&hv0.w); h[3] = f.x + f.y;
                f = __half22float2(*(__half2*)&hv1.x); h[4] = f.x + f.y;
                f = __half22float2(*(__half2*)&hv1.y); h[5] = f.x + f.y;
                f = __half22float2(*(__half2*)&hv1.z); h[6] = f.x + f.y;
                f = __half22float2(*(__half2*)&hv1.w); h[7] = f.x + f.y;
            }
            #pragma unroll
            for (int rr = 0; rr < 2; rr++) {
                uint4 wv = __ldg((const uint4*)(g_w16 + (size_t)(3 * HID + e0 + 12 + rr) * HID + k0));
                float2 w0 = __half22float2(*(__half2*)&wv.x);
                float2 w1 = __half22float2(*(__half2*)&wv.y);
                float2 w2 = __half22float2(*(__half2*)&wv.z);
                float2 w3 = __half22float2(*(__half2*)&wv.w);
                float acc = w0.x * h[0];
                acc = fmaf(w0.y, h[1], acc);
                acc = fmaf(w1.x, h[2], acc);
                acc = fmaf(w1.y, h[3], acc);
                acc = fmaf(w2.x, h[4], acc);
                acc = fmaf(w2.y, h[5], acc);
                acc = fmaf(w3.x, h[6], acc);
                acc = fmaf(w3.y, h[7], acc);
                #pragma unroll
                for (int o = 16; o > 0; o >>= 1)
                    acc += __shfl_xor_sync(0xffffffffu, acc, o);
                if (lane == 0) s_part[(54 + rr) * 8 + kc] = acc;
            }
        }
        __syncthreads();     // bar B

        // combine (warp 0 lanes < ne) -> publish tagged h FIRST -> hist/out after
        if (tid < ne) {
            float p[4];
            #pragma unroll
            for (int g = 0; g < 4; g++) {
                int rl = g * ne + tid;
                float4 q0 = *(const float4*)(s_part + rl * 8);
                float4 q1 = *(const float4*)(s_part + rl * 8 + 4);
                p[g] = ((q0.x + q0.y) + (q0.z + q0.w)) + ((q1.x + q1.y) + (q1.z + q1.w));
            }
            float fg = sigf(p[0] + gx0);
            float ig = sigf(p[1] + gx1);
            float gg = tanh_f(p[2] + gx2);
            float og = sigf(p[3] + gx3);
            c_state = fg * c_state + ig * gg;
            float hnew = og * tanh_f(c_state);
            int jj = e0 + tid;
            __half hi = __float2half_rn(hnew);
            __half lo = __float2half_rn(hnew - __half2float(hi));
            unsigned int h2v = (unsigned int)__half_as_ushort(hi)
                             | ((unsigned int)__half_as_ushort(lo) << 16);
            unsigned long long val = (unsigned long long)h2v
                                   | ((unsigned long long)(unsigned int)(t + 1) << 32);
            int buf = (t + 1) & 1;
            #pragma unroll
            for (int r = 0; r < NREP; r++)
                asm volatile("st.relaxed.gpu.global.b64 [%0], %1;"
                             :: "l"(&g_ht[buf][r][jj]), "l"(val) : "memory");
            g_hist[(size_t)t * HID + jj] = hnew;
            if (t == SEQ - 1) {
                d_out[(size_t)SEQ * NCHR + jj] = hnew;
                d_out[(size_t)SEQ * NCHR + HID + jj] = c_state;
            }
        }
        // no trailing barrier: next step's bar A provides all required ordering
    }
}

__global__ void __launch_bounds__(128)
logitsk(const float* __restrict__ Wfc, const float* __restrict__ bfc,
        float* __restrict__ out) {
    __shared__ float hs[16][129];
    const int t0 = blockIdx.x * 16;
    const int c = threadIdx.x;
    float acc[16];
    float bias = bfc[c];
    #pragma unroll
    for (int i = 0; i < 16; i++) acc[i] = bias;

    for (int k0 = 0; k0 < HID; k0 += 128) {
        __syncthreads();
        #pragma unroll
        for (int i = 0; i < 16; i++)
            hs[i][c] = g_hist[(size_t)(t0 + i) * HID + k0 + c];
        __syncthreads();
        #pragma unroll 4
        for (int kk = 0; kk < 128; kk++) {
            float wv = __ldg(Wfc + (size_t)c * HID + k0 + kk);
            #pragma unroll
            for (int i = 0; i < 16; i++)
                acc[i] = fmaf(hs[i][kk], wv, acc[i]);
        }
    }
    #pragma unroll
    for (int i = 0; i < 16; i++)
        out[(size_t)(t0 + i) * NCHR + c] = acc[i];
}

extern "C" void kernel_launch(void* const* d_in, const int* in_sizes, int n_in,
                              void* d_out, int out_size) {
    const int*   seq = (const int*)d_in[0];
    const float* emb = (const float*)d_in[1];
    const float* Wf  = (const float*)d_in[2];
    const float* bf  = (const float*)d_in[3];
    const float* Wi  = (const float*)d_in[4];
    const float* bi  = (const float*)d_in[5];
    const float* Wg  = (const float*)d_in[6];
    const float* bg  = (const float*)d_in[7];
    const float* Wo  = (const float*)d_in[8];
    const float* bo  = (const float*)d_in[9];
    const float* Wfc = (const float*)d_in[10];
    const float* bfc = (const float*)d_in[11];
    float* out = (float*)d_out;

    cudaFuncSetAttribute(lstm_persist,
                         cudaFuncAttributeMaxDynamicSharedMemorySize, SMEM_BYTES);

    embTk<<<(EMB * NCHR + 255) / 256, 256>>>(emb);                    // launch 0
    w16k<<<4 * HID, 256>>>(Wf, Wi, Wg, Wo);                           // launch 1 (+reset)
    gxk<<<4 * HID, 128>>>(Wf, Wi, Wg, Wo, bf, bi, bg, bo);            // launch 2
    lstm_persist<<<NCTA, TPB, SMEM_BYTES>>>(seq, out);                // launch 3 (ncu slot)
    logitsk<<<SEQ / 16, 128>>>(Wfc, bfc, out);                        // launch 4
}

// round 15
// speedup vs baseline: 1.0376x; 1.0152x over previous
#include <cuda_runtime.h>
#include <cuda_fp16.h>
#include <cstdint>

#define SEQ   16384
#define HID   2048
#define EMB   512
#define NCHR  128
#define FAN   2560
#define NCTA  148
#define TPB   1024
#define NREP  4

// smem layout (bytes)
#define S_W_OFF   0                 // 54 rows * 4096 = 221184
#define S_H_OFF   221184            // 2048 u32 (half2 hi,lo) = 8192
#define PART_OFF  229376            // 56 rows * 8 kc * 4B = 1792
#define FLAG_OFF  231168            // 32 u32 warp flags
#define SMEM_BYTES 231424

// tagged, replicated hidden state: u64 = { lo32 = half2(hi,lo), hi32 = step tag }
__device__ __align__(16) unsigned long long g_ht[2][NREP][HID];   // 128 KB
__device__ __align__(16) __half g_w16[4 * HID * HID];             // fp16 Wh, 32MB
__device__ __align__(16) float g_gx[NCHR * 4 * HID];
__device__ __align__(16) float g_embT[EMB * NCHR];
__device__ __align__(16) float g_hist[(size_t)SEQ * HID];

__device__ __forceinline__ float sigf(float x) { return 1.f / (1.f + __expf(-x)); }
__device__ __forceinline__ float tanh_f(float x) {
    x = fminf(fmaxf(x, -15.f), 15.f);
    float e = __expf(2.f * x);
    return (e - 1.f) / (e + 1.f);
}

__global__ void embTk(const float* __restrict__ emb) {
    int i = blockIdx.x * blockDim.x + threadIdx.x;
    if (i < EMB * NCHR) {
        int k = i / NCHR, c = i % NCHR;
        g_embT[(size_t)k * NCHR + c] = emb[(size_t)c * EMB + k];
    }
}

// fp16 weight conversion + per-call reset of tagged h buffers
__global__ void w16k(const float* __restrict__ Wf, const float* __restrict__ Wi,
                     const float* __restrict__ Wg, const float* __restrict__ Wo) {
    if (blockIdx.x < 8) {
        int i = blockIdx.x * 256 + threadIdx.x;
        #pragma unroll
        for (int r = 0; r < NREP; r++) {
            g_ht[0][r][i] = 0ull;                          // h=0, tag=0
            g_ht[1][r][i] = 0xFFFFFFFF00000000ull;         // invalid tag
        }
    }
    int rho = blockIdx.x;
    int g = rho >> 11, j = rho & 2047;
    const float* W = (g == 0) ? Wf : (g == 1) ? Wi : (g == 2) ? Wg : Wo;
    const float* row = W + (size_t)j * FAN + EMB;
    __half* dst = g_w16 + (size_t)rho * HID;
    for (int k = threadIdx.x; k < HID; k += 256)
        dst[k] = __float2half_rn(row[k]);
}

__global__ void gxk(const float* __restrict__ Wf, const float* __restrict__ Wi,
                    const float* __restrict__ Wg, const float* __restrict__ Wo,
                    const float* __restrict__ bf, const float* __restrict__ bi,
                    const float* __restrict__ bg, const float* __restrict__ bo) {
    int rho = blockIdx.x;
    int g = rho >> 11, j = rho & 2047;
    const float* W = (g == 0) ? Wf : (g == 1) ? Wi : (g == 2) ? Wg : Wo;
    const float* B = (g == 0) ? bf : (g == 1) ? bi : (g == 2) ? bg : bo;
    const float* row = W + (size_t)j * FAN;
    __shared__ float wx[EMB];
    for (int k = threadIdx.x; k < EMB; k += 128) wx[k] = row[k];
    __syncthreads();
    int c = threadIdx.x;
    float a0 = 0.f, a1 = 0.f, a2 = 0.f, a3 = 0.f;
    #pragma unroll 4
    for (int k = 0; k < EMB; k += 4) {
        a0 = fmaf(wx[k + 0], g_embT[(size_t)(k + 0) * NCHR + c], a0);
        a1 = fmaf(wx[k + 1], g_embT[(size_t)(k + 1) * NCHR + c], a1);
        a2 = fmaf(wx[k + 2], g_embT[(size_t)(k + 2) * NCHR + c], a2);
        a3 = fmaf(wx[k + 3], g_embT[(size_t)(k + 3) * NCHR + c], a3);
    }
    g_gx[(size_t)c * (4 * HID) + rho] = ((a0 + a1) + (a2 + a3)) + B[j];
}

__global__ void __launch_bounds__(TPB, 1)
lstm_persist(const int* __restrict__ seq, float* __restrict__ d_out) {
    extern __shared__ unsigned char smem[];
    float* s_part = (float*)(smem + PART_OFF);

    uint32_t sbase;
    asm("{ .reg .u64 t; cvta.to.shared.u64 t, %1; cvt.u32.u64 %0, t; }"
        : "=r"(sbase) : "l"(smem));

    const int b   = blockIdx.x;
    const int tid = threadIdx.x;
    const int ne  = (b < 124) ? 14 : 13;
    const int e0  = (b < 124) ? 14 * b : 1736 + 13 * (b - 124);
    const int nrows = 4 * ne;
    const int rows_smem = (nrows < 54) ? nrows : 54;
    const int rep = b & (NREP - 1);

    // fp16 weight rows -> SMEM, 16B-granule XOR swizzle per row
    for (int i = tid; i < rows_smem * 256; i += TPB) {
        int rl = i >> 8, gi = i & 255;
        int G = (rl / ne) * HID + e0 + (rl % ne);
        uint4 v = ((const uint4*)(g_w16 + (size_t)G * HID))[gi];
        uint32_t off = rl * 4096 + ((gi * 16) ^ ((rl & 7) << 4));
        *(uint4*)(smem + S_W_OFF + off) = v;
    }
    if (tid < 32) *(unsigned int*)(smem + FLAG_OFF + tid * 4) = 0u;

    const int w = tid >> 5, lane = tid & 31;
    const int tile = w >> 3;            // m-tile 0..3
    const int kc   = w & 7;             // k-chunk of 256
    const int sgrp = w >> 2;            // staging group (elements [256*sgrp, +256))

    int rl_lane = tile * 16 + (lane & 15);
    if (rl_lane >= rows_smem) rl_lane = tile * 16;
    const uint32_t swz = (uint32_t)((rl_lane & 7) << 4);
    const uint32_t klo16 = (lane >= 16) ? 16u : 0u;
    const uint32_t a_base = sbase + S_W_OFF + (uint32_t)rl_lane * 4096;

    const uint32_t sel = (lane < 4) ? 0x5410u : 0x7632u;
    const int kbase = kc * 256 + (lane & 3) * 2;
    const uint32_t flag_my = sbase + FLAG_OFF + (uint32_t)w * 4;
    const uint32_t flag_ln = sbase + FLAG_OFF + (uint32_t)lane * 4;

    float c_state = 0.f;
    __syncthreads();

    for (int t = 0; t < SEQ; t++) {
        // gx prefetch (h-independent; overlaps the staging poll)
        float gx0 = 0.f, gx1 = 0.f, gx2 = 0.f, gx3 = 0.f;
        if (tid < ne) {
            int ch = __ldg(seq + t);
            const float* gp = g_gx + (size_t)ch * (4 * HID) + e0 + tid;
            gx0 = __ldg(gp);
            gx1 = __ldg(gp + HID);
            gx2 = __ldg(gp + 2 * HID);
            gx3 = __ldg(gp + 3 * HID);
        }

        // ---- tagged staging, interleaved dual poll (both loads in flight)
        {
            const unsigned long long* p0 = &g_ht[t & 1][rep][2 * tid];
            const unsigned int tg = (unsigned int)t;
            unsigned long long v0 = 0, v1 = 0;
            unsigned int ok0 = 0, ok1 = 0;
            do {
                if (!ok0) {
                    asm volatile("ld.relaxed.gpu.global.b64 %0, [%1];"
                                 : "=l"(v0) : "l"(p0) : "memory");
                    ok0 = ((unsigned int)(v0 >> 32) == tg);
                }
                if (!ok1) {
                    asm volatile("ld.relaxed.gpu.global.b64 %0, [%1];"
                                 : "=l"(v1) : "l"(p0 + 1) : "memory");
                    ok1 = ((unsigned int)(v1 >> 32) == tg);
                }
            } while (!(ok0 & ok1));
            *(uint2*)(smem + S_H_OFF + tid * 8) =
                make_uint2((unsigned int)v0, (unsigned int)v1);
        }
        // per-chunk producer/consumer barriers (count=256 each: 8 warp-slots)
        asm volatile("bar.arrive %0, 256;" :: "r"(1 + sgrp) : "memory");
        asm volatile("bar.sync %0, 256;"   :: "r"(1 + kc)   : "memory");

        // ---- HMMA mainloop: 16 k-tiles, 2 accumulator chains
        float c0 = 0.f, c1 = 0.f, c2 = 0.f, c3 = 0.f;
        float d0 = 0.f, d1 = 0.f, d2 = 0.f, d3 = 0.f;
        #pragma unroll
        for (int kt = 0; kt < 16; kt++) {
            uint32_t byt = (uint32_t)(kc * 512 + kt * 32) + klo16;
            uint32_t a_addr = a_base + (byt ^ swz);
            uint32_t a0, a1, a2, a3;
            asm volatile("ldmatrix.sync.aligned.m8n8.x4.shared.b16 {%0,%1,%2,%3}, [%4];"
                         : "=r"(a0), "=r"(a1), "=r"(a2), "=r"(a3) : "r"(a_addr));
            uint32_t bb0 = 0u, bb1 = 0u;
            if (lane < 8) {
                uint2 v0 = *(const uint2*)(smem + S_H_OFF + (kbase + kt * 16) * 4);
                uint2 v1 = *(const uint2*)(smem + S_H_OFF + (kbase + kt * 16 + 8) * 4);
                asm("prmt.b32 %0, %1, %2, %3;" : "=r"(bb0) : "r"(v0.x), "r"(v0.y), "r"(sel));
                asm("prmt.b32 %0, %1, %2, %3;" : "=r"(bb1) : "r"(v1.x), "r"(v1.y), "r"(sel));
            }
            if (kt & 1)
                asm volatile("mma.sync.aligned.m16n8k16.row.col.f32.f16.f16.f32 "
                             "{%0,%1,%2,%3}, {%4,%5,%6,%7}, {%8,%9}, {%0,%1,%2,%3};"
                             : "+f"(d0), "+f"(d1), "+f"(d2), "+f"(d3)
                             : "r"(a0), "r"(a1), "r"(a2), "r"(a3), "r"(bb0), "r"(bb1));
            else
                asm volatile("mma.sync.aligned.m16n8k16.row.col.f32.f16.f16.f32 "
                             "{%0,%1,%2,%3}, {%4,%5,%6,%7}, {%8,%9}, {%0,%1,%2,%3};"
                             : "+f"(c0), "+f"(c1), "+f"(c2), "+f"(c3)
                             : "r"(a0), "r"(a1), "r"(a2), "r"(a3), "r"(bb0), "r"(bb1));
        }
        c0 += d0; c1 += d1; c2 += d2; c3 += d3;

        if ((lane & 3) == 0) {
            int r0 = tile * 16 + (lane >> 2), r1 = r0 + 8;
            if (r0 < rows_smem) s_part[r0 * 8 + kc] = c0 + c1;
            if (r1 < rows_smem) s_part[r1 * 8 + kc] = c2 + c3;
        }

        // overflow rows 54,55 (ne==14): FFMA side-path (L2 weights, staged h2)
        if (ne == 14 && tile == 3) {
            int k0 = kc * 256 + lane * 8;
            uint4 hv0 = *(const uint4*)(smem + S_H_OFF + k0 * 4);
            uint4 hv1 = *(const uint4*)(smem + S_H_OFF + k0 * 4 + 16);
            float h[8];
            {
                float2 f;
                f = __half22float2(*(__half2*)&hv0.x); h[0] = f.x + f.y;
                f = __half22float2(*(__half2*)&hv0.y); h[1] = f.x + f.y;
                f = __half22float2(*(__half2*)&hv0.z); h[2] = f.x + f.y;
                f = __half22float2(*(__half2*)&hv0.w); h[3] = f.x + f.y;
                f = __half22float2(*(__half2*)&hv1.x); h[4] = f.x + f.y;
                f = __half22float2(*(__half2*)&hv1.y); h[5] = f.x + f.y;
                f = __half22float2(*(__half2*)&hv1.z); h[6] = f.x + f.y;
                f = __half22float2(*(__half2*)&hv1.w); h[7] = f.x + f.y;
            }
            #pragma unroll
            for (int rr = 0; rr < 2; rr++) {
                uint4 wv = __ldg((const uint4*)(g_w16 + (size_t)(3 * HID + e0 + 12 + rr) * HID + k0));
                float2 w0 = __half22float2(*(__half2*)&wv.x);
                float2 w1 = __half22float2(*(__half2*)&wv.y);
                float2 w2 = __half22float2(*(__half2*)&wv.z);
                float2 w3 = __half22float2(*(__half2*)&wv.w);
                float acc = w0.x * h[0];
                acc = fmaf(w0.y, h[1], acc);
                acc = fmaf(w1.x, h[2], acc);
                acc = fmaf(w1.y, h[3], acc);
                acc = fmaf(w2.x, h[4], acc);
                acc = fmaf(w2.y, h[5], acc);
                acc = fmaf(w3.x, h[6], acc);
                acc = fmaf(w3.y, h[7], acc);
                #pragma unroll
                for (int o = 16; o > 0; o >>= 1)
                    acc += __shfl_xor_sync(0xffffffffu, acc, o);
                if (lane == 0) s_part[(54 + rr) * 8 + kc] = acc;
            }
        }

        // publish this warp's partials: release-flag (replaces bar B)
        if (lane == 0)
            asm volatile("st.release.cta.shared::cta.u32 [%0], %1;"
                         :: "r"(flag_my), "r"((unsigned int)(t + 1)) : "memory");

        // ---- combine (warp 0): poll all 32 warp flags, then reduce+activate+publish
        if (w == 0) {
            const unsigned int want = (unsigned int)(t + 1);
            unsigned int fv;
            do {
                asm volatile("ld.acquire.cta.shared::cta.u32 %0, [%1];"
                             : "=r"(fv) : "r"(flag_ln) : "memory");
            } while (fv != want);
            __syncwarp();
            if (lane < ne) {
                float p[4];
                #pragma unroll
                for (int g = 0; g < 4; g++) {
                    int rl = g * ne + lane;
                    float4 q0 = *(const float4*)(s_part + rl * 8);
                    float4 q1 = *(const float4*)(s_part + rl * 8 + 4);
                    p[g] = ((q0.x + q0.y) + (q0.z + q0.w)) + ((q1.x + q1.y) + (q1.z + q1.w));
                }
                float fg = sigf(p[0] + gx0);
                float ig = sigf(p[1] + gx1);
                float gg = tanh_f(p[2] + gx2);
                float og = sigf(p[3] + gx3);
                c_state = fg * c_state + ig * gg;
                float hnew = og * tanh_f(c_state);
                int jj = e0 + lane;
                __half hi = __float2half_rn(hnew);
                __half lo = __float2half_rn(hnew - __half2float(hi));
                unsigned int h2v = (unsigned int)__half_as_ushort(hi)
                                 | ((unsigned int)__half_as_ushort(lo) << 16);
                unsigned long long val = (unsigned long long)h2v
                                       | ((unsigned long long)(unsigned int)(t + 1) << 32);
                int buf = (t + 1) & 1;
                #pragma unroll
                for (int r = 0; r < NREP; r++)
                    asm volatile("st.relaxed.gpu.global.b64 [%0], %1;"
                                 :: "l"(&g_ht[buf][r][jj]), "l"(val) : "memory");
                g_hist[(size_t)t * HID + jj] = hnew;
                if (t == SEQ - 1) {
                    d_out[(size_t)SEQ * NCHR + jj] = hnew;
                    d_out[(size_t)SEQ * NCHR + HID + jj] = c_state;
                }
            }
        }
        // no trailing barrier: the tag chain + next step's barriers order everything
    }
}

__global__ void __launch_bounds__(128)
logitsk(const float* __restrict__ Wfc, const float* __restrict__ bfc,
        float* __restrict__ out) {
    __shared__ float hs[16][129];
    const int t0 = blockIdx.x * 16;
    const int c = threadIdx.x;
    float acc[16];
    float bias = bfc[c];
    #pragma unroll
    for (int i = 0; i < 16; i++) acc[i] = bias;

    for (int k0 = 0; k0 < HID; k0 += 128) {
        __syncthreads();
        #pragma unroll
        for (int i = 0; i < 16; i++)
            hs[i][c] = g_hist[(size_t)(t0 + i) * HID + k0 + c];
        __syncthreads();
        #pragma unroll 4
        for (int kk = 0; kk < 128; kk++) {
            float wv = __ldg(Wfc + (size_t)c * HID + k0 + kk);
            #pragma unroll
            for (int i = 0; i < 16; i++)
                acc[i] = fmaf(hs[i][kk], wv, acc[i]);
        }
    }
    #pragma unroll
    for (int i = 0; i < 16; i++)
        out[(size_t)(t0 + i) * NCHR + c] = acc[i];
}

extern "C" void kernel_launch(void* const* d_in, const int* in_sizes, int n_in,
                              void* d_out, int out_size) {
    const int*   seq = (const int*)d_in[0];
    const float* emb = (const float*)d_in[1];
    const float* Wf  = (const float*)d_in[2];
    const float* bf  = (const float*)d_in[3];
    const float* Wi  = (const float*)d_in[4];
    const float* bi  = (const float*)d_in[5];
    const float* Wg  = (const float*)d_in[6];
    const float* bg  = (const float*)d_in[7];
    const float* Wo  = (const float*)d_in[8];
    const float* bo  = (const float*)d_in[9];
    const float* Wfc = (const float*)d_in[10];
    const float* bfc = (const float*)d_in[11];
    float* out = (float*)d_out;

    cudaFuncSetAttribute(lstm_persist,
                         cudaFuncAttributeMaxDynamicSharedMemorySize, SMEM_BYTES);

    embTk<<<(EMB * NCHR + 255) / 256, 256>>>(emb);                    // launch 0
    w16k<<<4 * HID, 256>>>(Wf, Wi, Wg, Wo);                           // launch 1 (+reset)
    gxk<<<4 * HID, 128>>>(Wf, Wi, Wg, Wo, bf, bi, bg, bo);            // launch 2
    lstm_persist<<<NCTA, TPB, SMEM_BYTES>>>(seq, out);                // launch 3 (ncu slot)
    logitsk<<<SEQ / 16, 128>>>(Wfc, bfc, out);                        // launch 4
}